// round 3
// baseline (speedup 1.0000x reference)
#include <cuda_runtime.h>
#include <cuda_bf16.h>
#include <cstdint>
#include <cstddef>

// Problem constants
#define B_    4
#define Hdim  256
#define Wdim  256
#define C_    256
#define NH_   8
#define HD_   32
#define WS_   8
#define Mtot  262144          // B * H * W tokens
#define NWIN  4096            // B * 32 * 32 windows

// Scratch (allocation-free rule: __device__ globals)
__device__ float g_qkv[(size_t)Mtot * 768];   // natural token order, [M, 768] (q|k|v each 256)
__device__ float g_att[(size_t)Mtot * 256];   // attention output, natural token order

// ---------------------------------------------------------------------------
// helpers
// ---------------------------------------------------------------------------
__device__ __forceinline__ float tf32r(float x) {
    uint32_t u;
    asm("cvt.rna.tf32.f32 %0, %1;" : "=r"(u) : "f"(x));
    return __uint_as_float(u);
}

__device__ __forceinline__ void mma8(float c[4], const uint32_t a[4], const uint32_t b[2]) {
    asm volatile(
        "mma.sync.aligned.m16n8k8.row.col.f32.tf32.tf32.f32 "
        "{%0,%1,%2,%3}, {%4,%5,%6,%7}, {%8,%9}, {%0,%1,%2,%3};\n"
        : "+f"(c[0]), "+f"(c[1]), "+f"(c[2]), "+f"(c[3])
        : "r"(a[0]), "r"(a[1]), "r"(a[2]), "r"(a[3]), "r"(b[0]), "r"(b[1]));
}

// ---------------------------------------------------------------------------
// Generic TF32 GEMM:  C[M,N] = A[M,K] @ B[N,K]^T (+ bias[N])
// BM=128, BN=128, BK=16, 256 threads, 8 warps (2x4), warp tile 64x32
// ---------------------------------------------------------------------------
#define BM 128
#define BN 128
#define BK 16

__global__ __launch_bounds__(256) void gemm_tf32(
    const float* __restrict__ A, const float* __restrict__ Bm,
    const float* __restrict__ bias, float* __restrict__ C,
    int M, int N, int K)
{
    __shared__ float As[BK][BM + 4];
    __shared__ float Bs[BK][BN + 4];

    const int tid  = threadIdx.x;
    const int mT   = blockIdx.y * BM;
    const int nT   = blockIdx.x * BN;
    const int lane = tid & 31;
    const int warp = tid >> 5;
    const int gid  = lane >> 2;
    const int tig  = lane & 3;
    const int wm   = (warp & 1) * 64;
    const int wn   = (warp >> 1) * 32;

    float c[4][4][4];
#pragma unroll
    for (int i = 0; i < 4; i++)
#pragma unroll
        for (int j = 0; j < 4; j++)
#pragma unroll
            for (int r = 0; r < 4; r++) c[i][j][r] = 0.f;

    for (int k0 = 0; k0 < K; k0 += BK) {
#pragma unroll
        for (int it = 0; it < 2; it++) {
            int v   = tid + it * 256;           // 0..511
            int row = v >> 2;                   // 0..127
            int c4  = (v & 3) * 4;              // 0,4,8,12
            float4 a4 = *(const float4*)(A  + (size_t)(mT + row) * K + k0 + c4);
            float4 b4 = *(const float4*)(Bm + (size_t)(nT + row) * K + k0 + c4);
            As[c4 + 0][row] = tf32r(a4.x);
            As[c4 + 1][row] = tf32r(a4.y);
            As[c4 + 2][row] = tf32r(a4.z);
            As[c4 + 3][row] = tf32r(a4.w);
            Bs[c4 + 0][row] = tf32r(b4.x);
            Bs[c4 + 1][row] = tf32r(b4.y);
            Bs[c4 + 2][row] = tf32r(b4.z);
            Bs[c4 + 3][row] = tf32r(b4.w);
        }
        __syncthreads();

#pragma unroll
        for (int kk = 0; kk < BK; kk += 8) {
            uint32_t af[4][4], bf[4][2];
#pragma unroll
            for (int mf = 0; mf < 4; mf++) {
                int m = wm + mf * 16 + gid;
                af[mf][0] = __float_as_uint(As[kk + tig    ][m]);
                af[mf][1] = __float_as_uint(As[kk + tig    ][m + 8]);
                af[mf][2] = __float_as_uint(As[kk + tig + 4][m]);
                af[mf][3] = __float_as_uint(As[kk + tig + 4][m + 8]);
            }
#pragma unroll
            for (int nf = 0; nf < 4; nf++) {
                int n = wn + nf * 8 + gid;
                bf[nf][0] = __float_as_uint(Bs[kk + tig    ][n]);
                bf[nf][1] = __float_as_uint(Bs[kk + tig + 4][n]);
            }
#pragma unroll
            for (int mf = 0; mf < 4; mf++)
#pragma unroll
                for (int nf = 0; nf < 4; nf++)
                    mma8(c[mf][nf], af[mf], bf[nf]);
        }
        __syncthreads();
    }

    // epilogue
#pragma unroll
    for (int mf = 0; mf < 4; mf++) {
#pragma unroll
        for (int nf = 0; nf < 4; nf++) {
            int row = mT + wm + mf * 16 + gid;
            int col = nT + wn + nf * 8 + 2 * tig;
            float b0 = 0.f, b1 = 0.f;
            if (bias) { b0 = bias[col]; b1 = bias[col + 1]; }
            float2 r0 = make_float2(c[mf][nf][0] + b0, c[mf][nf][1] + b1);
            float2 r1 = make_float2(c[mf][nf][2] + b0, c[mf][nf][3] + b1);
            *(float2*)(C + (size_t)row * N + col)       = r0;
            *(float2*)(C + (size_t)(row + 8) * N + col) = r1;
        }
    }
}

// ---------------------------------------------------------------------------
// Window attention: one CTA per (window, head), 128 threads (4 warps).
// Gathers q,k,v for the 64 window tokens, computes softmax(q k^T * s + bias) v
// with TF32 MMAs, scatters result to natural token order in g_att.
// ---------------------------------------------------------------------------
__global__ __launch_bounds__(128) void win_attn(
    const float* __restrict__ qkv, const float* __restrict__ bias,
    float* __restrict__ outp)
{
    __shared__ float Qs[64][36];
    __shared__ float Ks[64][36];
    __shared__ float Vs[64][36];
    __shared__ float Ss[64][68];

    const int w   = blockIdx.x;
    const int h   = blockIdx.y;
    const int b   = w >> 10;
    const int rem = w & 1023;
    const int wh  = rem >> 5;
    const int ww  = rem & 31;
    const int base_l = (b << 16) + (wh << 3) * 256 + (ww << 3);

    const int tid = threadIdx.x;
    const float scale = 0.17677669529663687f;   // 1/sqrt(32)

    // load q,k,v tiles (64 x 32 each), row-coalesced float4
#pragma unroll
    for (int it = 0; it < 4; it++) {
        int v   = tid + it * 128;               // 0..511
        int row = v >> 3;                       // token 0..63
        int c4  = (v & 7) << 2;                 // 0..28
        int l   = base_l + ((row >> 3) << 8) + (row & 7);
        const float* rp = qkv + (size_t)l * 768 + (h << 5) + c4;
        float4 q4 = *(const float4*)(rp);
        float4 k4 = *(const float4*)(rp + 256);
        float4 v4 = *(const float4*)(rp + 512);
        Qs[row][c4 + 0] = tf32r(q4.x * scale);
        Qs[row][c4 + 1] = tf32r(q4.y * scale);
        Qs[row][c4 + 2] = tf32r(q4.z * scale);
        Qs[row][c4 + 3] = tf32r(q4.w * scale);
        Ks[row][c4 + 0] = tf32r(k4.x);
        Ks[row][c4 + 1] = tf32r(k4.y);
        Ks[row][c4 + 2] = tf32r(k4.z);
        Ks[row][c4 + 3] = tf32r(k4.w);
        Vs[row][c4 + 0] = tf32r(v4.x);
        Vs[row][c4 + 1] = tf32r(v4.y);
        Vs[row][c4 + 2] = tf32r(v4.z);
        Vs[row][c4 + 3] = tf32r(v4.w);
    }
    __syncthreads();

    const int lane = tid & 31, warp = tid >> 5;
    const int gid = lane >> 2, tig = lane & 3;
    const int mB = warp << 4;
    const int r0 = mB + gid, r1 = r0 + 8;

    // S = q*scale @ k^T  (64x64, each warp 16 rows)
    float c[8][4];
#pragma unroll
    for (int nf = 0; nf < 8; nf++)
#pragma unroll
        for (int r = 0; r < 4; r++) c[nf][r] = 0.f;

#pragma unroll
    for (int kc = 0; kc < 4; kc++) {
        uint32_t a[4];
        a[0] = __float_as_uint(Qs[r0][kc * 8 + tig]);
        a[1] = __float_as_uint(Qs[r1][kc * 8 + tig]);
        a[2] = __float_as_uint(Qs[r0][kc * 8 + tig + 4]);
        a[3] = __float_as_uint(Qs[r1][kc * 8 + tig + 4]);
#pragma unroll
        for (int nf = 0; nf < 8; nf++) {
            uint32_t bf[2];
            bf[0] = __float_as_uint(Ks[nf * 8 + gid][kc * 8 + tig]);
            bf[1] = __float_as_uint(Ks[nf * 8 + gid][kc * 8 + tig + 4]);
            mma8(c[nf], a, bf);
        }
    }

    // + bias, then row softmax (row r0 in c[.][0..1], row r1 in c[.][2..3])
    const float* bp = bias + (h << 12);
    float mx0 = -1e30f, mx1 = -1e30f;
#pragma unroll
    for (int nf = 0; nf < 8; nf++) {
        int col = nf * 8 + 2 * tig;
        float2 b0 = *(const float2*)(bp + r0 * 64 + col);
        float2 b1 = *(const float2*)(bp + r1 * 64 + col);
        c[nf][0] += b0.x; c[nf][1] += b0.y;
        c[nf][2] += b1.x; c[nf][3] += b1.y;
        mx0 = fmaxf(mx0, fmaxf(c[nf][0], c[nf][1]));
        mx1 = fmaxf(mx1, fmaxf(c[nf][2], c[nf][3]));
    }
    mx0 = fmaxf(mx0, __shfl_xor_sync(0xffffffffu, mx0, 1));
    mx0 = fmaxf(mx0, __shfl_xor_sync(0xffffffffu, mx0, 2));
    mx1 = fmaxf(mx1, __shfl_xor_sync(0xffffffffu, mx1, 1));
    mx1 = fmaxf(mx1, __shfl_xor_sync(0xffffffffu, mx1, 2));

    float s0 = 0.f, s1 = 0.f;
#pragma unroll
    for (int nf = 0; nf < 8; nf++) {
        c[nf][0] = __expf(c[nf][0] - mx0); s0 += c[nf][0];
        c[nf][1] = __expf(c[nf][1] - mx0); s0 += c[nf][1];
        c[nf][2] = __expf(c[nf][2] - mx1); s1 += c[nf][2];
        c[nf][3] = __expf(c[nf][3] - mx1); s1 += c[nf][3];
    }
    s0 += __shfl_xor_sync(0xffffffffu, s0, 1);
    s0 += __shfl_xor_sync(0xffffffffu, s0, 2);
    s1 += __shfl_xor_sync(0xffffffffu, s1, 1);
    s1 += __shfl_xor_sync(0xffffffffu, s1, 2);
    float i0 = 1.f / s0, i1 = 1.f / s1;

#pragma unroll
    for (int nf = 0; nf < 8; nf++) {
        int col = nf * 8 + 2 * tig;
        Ss[r0][col]     = tf32r(c[nf][0] * i0);
        Ss[r0][col + 1] = tf32r(c[nf][1] * i0);
        Ss[r1][col]     = tf32r(c[nf][2] * i1);
        Ss[r1][col + 1] = tf32r(c[nf][3] * i1);
    }
    __syncthreads();

    // O = P @ V  (64x32, each warp 16 rows)
    float o[4][4];
#pragma unroll
    for (int nf = 0; nf < 4; nf++)
#pragma unroll
        for (int r = 0; r < 4; r++) o[nf][r] = 0.f;

#pragma unroll
    for (int kc = 0; kc < 8; kc++) {
        uint32_t a[4];
        a[0] = __float_as_uint(Ss[r0][kc * 8 + tig]);
        a[1] = __float_as_uint(Ss[r1][kc * 8 + tig]);
        a[2] = __float_as_uint(Ss[r0][kc * 8 + tig + 4]);
        a[3] = __float_as_uint(Ss[r1][kc * 8 + tig + 4]);
#pragma unroll
        for (int nf = 0; nf < 4; nf++) {
            uint32_t bf[2];
            bf[0] = __float_as_uint(Vs[kc * 8 + tig    ][nf * 8 + gid]);
            bf[1] = __float_as_uint(Vs[kc * 8 + tig + 4][nf * 8 + gid]);
            mma8(o[nf], a, bf);
        }
    }

    // scatter to natural token order, [M, 256] at col h*32 + d
    const int l0 = base_l + ((r0 >> 3) << 8) + (r0 & 7);
    const int l1 = base_l + ((r1 >> 3) << 8) + (r1 & 7);
#pragma unroll
    for (int nf = 0; nf < 4; nf++) {
        int col = (h << 5) + nf * 8 + 2 * tig;
        *(float2*)(outp + (size_t)l0 * 256 + col) = make_float2(o[nf][0], o[nf][1]);
        *(float2*)(outp + (size_t)l1 * 256 + col) = make_float2(o[nf][2], o[nf][3]);
    }
}

// ---------------------------------------------------------------------------
// launch
// ---------------------------------------------------------------------------
extern "C" void kernel_launch(void* const* d_in, const int* in_sizes, int n_in,
                              void* d_out, int out_size)
{
    const float* x      = (const float*)d_in[0];
    const float* qkv_w  = (const float*)d_in[1];
    const float* proj_w = (const float*)d_in[2];
    const float* proj_b = (const float*)d_in[3];
    const float* bias   = (const float*)d_in[4];
    float* out = (float*)d_out;

    float *qkv_p, *att_p;
    cudaGetSymbolAddress((void**)&qkv_p, g_qkv);
    cudaGetSymbolAddress((void**)&att_p, g_att);

    // QKV projection: [262144,256] @ [768,256]^T -> [262144,768]
    gemm_tf32<<<dim3(768 / BN, Mtot / BM), 256>>>(x, qkv_w, nullptr, qkv_p,
                                                  Mtot, 768, C_);
    // window attention
    win_attn<<<dim3(NWIN, NH_), 128>>>(qkv_p, bias, att_p);
    // output projection: [262144,256] @ [256,256]^T + b -> d_out
    gemm_tf32<<<dim3(256 / BN, Mtot / BM), 256>>>(att_p, proj_w, proj_b, out,
                                                  Mtot, C_, C_);
}

// round 5
// speedup vs baseline: 1.2950x; 1.2950x over previous
#include <cuda_runtime.h>
#include <cuda_bf16.h>
#include <cstdint>
#include <cstddef>

// Problem constants
#define B_    4
#define Hdim  256
#define Wdim  256
#define C_    256
#define NH_   8
#define HD_   32
#define WS_   8
#define Mtot  262144          // B * H * W tokens
#define NWIN  4096            // B * 32 * 32 windows

// Scratch (allocation-free rule: __device__ globals)
__device__ float g_qkv[(size_t)Mtot * 768];   // natural token order, [M, 768] (q|k|v)
__device__ float g_att[(size_t)Mtot * 256];   // attention output, natural token order

// ---------------------------------------------------------------------------
// helpers
// ---------------------------------------------------------------------------
__device__ __forceinline__ float tf32r(float x) {
    uint32_t u;
    asm("cvt.rna.tf32.f32 %0, %1;" : "=r"(u) : "f"(x));
    return __uint_as_float(u);
}
__device__ __forceinline__ uint32_t tf32u(float x) {
    uint32_t u;
    asm("cvt.rna.tf32.f32 %0, %1;" : "=r"(u) : "f"(x));
    return u;
}

__device__ __forceinline__ void mma8(float c[4], const uint32_t a[4], const uint32_t b[2]) {
    asm volatile(
        "mma.sync.aligned.m16n8k8.row.col.f32.tf32.tf32.f32 "
        "{%0,%1,%2,%3}, {%4,%5,%6,%7}, {%8,%9}, {%0,%1,%2,%3};\n"
        : "+f"(c[0]), "+f"(c[1]), "+f"(c[2]), "+f"(c[3])
        : "r"(a[0]), "r"(a[1]), "r"(a[2]), "r"(a[3]), "r"(b[0]), "r"(b[1]));
}

__device__ __forceinline__ void cpa16(void* dst, const void* src) {
    uint32_t d = (uint32_t)__cvta_generic_to_shared(dst);
    asm volatile("cp.async.cg.shared.global [%0], [%1], 16;\n" :: "r"(d), "l"(src));
}
__device__ __forceinline__ void cpa_commit() {
    asm volatile("cp.async.commit_group;\n" ::: "memory");
}
template <int N>
__device__ __forceinline__ void cpa_wait() {
    asm volatile("cp.async.wait_group %0;\n" :: "n"(N) : "memory");
}

// ---------------------------------------------------------------------------
// TF32 GEMM with 2-stage cp.async pipeline:
// C[M,N] = A[M,K] @ B[N,K]^T (+ bias[N])
// BM=128, BN=128, BK=16, 256 threads, 8 warps (2x4), warp tile 64x32
// smem tiles row-major [rows][BK+8] (96B stride, cp.async 16B chunks)
// ---------------------------------------------------------------------------
#define BM 128
#define BN 128
#define BK 16
#define KPAD (BK + 8)   // 24 floats = 96 bytes (16B multiple)

__global__ __launch_bounds__(256) void gemm_tf32(
    const float* __restrict__ A, const float* __restrict__ Bm,
    const float* __restrict__ bias, float* __restrict__ C,
    int M, int N, int K)
{
    __shared__ __align__(16) float As[2][BM][KPAD];
    __shared__ __align__(16) float Bs[2][BN][KPAD];

    const int tid  = threadIdx.x;
    const int mT   = blockIdx.y * BM;
    const int nT   = blockIdx.x * BN;
    const int lane = tid & 31;
    const int warp = tid >> 5;
    const int gid  = lane >> 2;
    const int tig  = lane & 3;
    const int wm   = (warp & 1) * 64;
    const int wn   = (warp >> 1) * 32;

    float c[4][4][4];
#pragma unroll
    for (int i = 0; i < 4; i++)
#pragma unroll
        for (int j = 0; j < 4; j++)
#pragma unroll
            for (int r = 0; r < 4; r++) c[i][j][r] = 0.f;

    // copy map: 512 float4 per tile, 2 per thread
    const int r0c = tid >> 2;            // 0..63   (rows for v0)
    const int c0c = (tid & 3) << 2;      // 0,4,8,12
    const int r1c = r0c + 64;            // rows for v1

    auto issue = [&](int s, int k0) {
        const float* a0 = A  + (size_t)(mT + r0c) * K + k0 + c0c;
        const float* a1 = A  + (size_t)(mT + r1c) * K + k0 + c0c;
        const float* b0 = Bm + (size_t)(nT + r0c) * K + k0 + c0c;
        const float* b1 = Bm + (size_t)(nT + r1c) * K + k0 + c0c;
        cpa16(&As[s][r0c][c0c], a0);
        cpa16(&As[s][r1c][c0c], a1);
        cpa16(&Bs[s][r0c][c0c], b0);
        cpa16(&Bs[s][r1c][c0c], b1);
        cpa_commit();
    };

    issue(0, 0);
    const int NT = K >> 4;

    for (int kt = 0; kt < NT; kt++) {
        if (kt + 1 < NT) {
            issue((kt + 1) & 1, (kt + 1) * BK);
            cpa_wait<1>();
        } else {
            cpa_wait<0>();
        }
        __syncthreads();

        const int s = kt & 1;
#pragma unroll
        for (int kk = 0; kk < BK; kk += 8) {
            uint32_t af[4][4], bf[4][2];
#pragma unroll
            for (int mf = 0; mf < 4; mf++) {
                int m = wm + mf * 16 + gid;
                af[mf][0] = tf32u(As[s][m    ][kk + tig]);
                af[mf][1] = tf32u(As[s][m + 8][kk + tig]);
                af[mf][2] = tf32u(As[s][m    ][kk + tig + 4]);
                af[mf][3] = tf32u(As[s][m + 8][kk + tig + 4]);
            }
#pragma unroll
            for (int nf = 0; nf < 4; nf++) {
                int n = wn + nf * 8 + gid;
                bf[nf][0] = tf32u(Bs[s][n][kk + tig]);
                bf[nf][1] = tf32u(Bs[s][n][kk + tig + 4]);
            }
#pragma unroll
            for (int mf = 0; mf < 4; mf++)
#pragma unroll
                for (int nf = 0; nf < 4; nf++)
                    mma8(c[mf][nf], af[mf], bf[nf]);
        }
        __syncthreads();
    }

    // epilogue
#pragma unroll
    for (int mf = 0; mf < 4; mf++) {
#pragma unroll
        for (int nf = 0; nf < 4; nf++) {
            int row = mT + wm + mf * 16 + gid;
            int col = nT + wn + nf * 8 + 2 * tig;
            float b0 = 0.f, b1 = 0.f;
            if (bias) { b0 = bias[col]; b1 = bias[col + 1]; }
            float2 v0 = make_float2(c[mf][nf][0] + b0, c[mf][nf][1] + b1);
            float2 v1 = make_float2(c[mf][nf][2] + b0, c[mf][nf][3] + b1);
            *(float2*)(C + (size_t)row * N + col)       = v0;
            *(float2*)(C + (size_t)(row + 8) * N + col) = v1;
        }
    }
}

// ---------------------------------------------------------------------------
// Window attention: one CTA per (window, head), 128 threads (4 warps).
// Gathers q,k,v for the 64 window tokens, computes softmax(q k^T * s + bias) v
// with TF32 MMAs, scatters result to natural token order in g_att.
// ---------------------------------------------------------------------------
__global__ __launch_bounds__(128) void win_attn(
    const float* __restrict__ qkv, const float* __restrict__ bias,
    float* __restrict__ outp)
{
    __shared__ float Qs[64][36];
    __shared__ float Ks[64][36];
    __shared__ float Vs[64][36];
    __shared__ float Ss[64][68];

    const int w   = blockIdx.x;
    const int h   = blockIdx.y;
    const int b   = w >> 10;
    const int rem = w & 1023;
    const int wh  = rem >> 5;
    const int ww  = rem & 31;
    const int base_l = (b << 16) + (wh << 3) * 256 + (ww << 3);

    const int tid = threadIdx.x;
    const float scale = 0.17677669529663687f;   // 1/sqrt(32)

    // load q,k,v tiles (64 x 32 each), row-coalesced float4
#pragma unroll
    for (int it = 0; it < 4; it++) {
        int v   = tid + it * 128;               // 0..511
        int row = v >> 3;                       // token 0..63
        int c4  = (v & 7) << 2;                 // 0..28
        int l   = base_l + ((row >> 3) << 8) + (row & 7);
        const float* rp = qkv + (size_t)l * 768 + (h << 5) + c4;
        float4 q4 = *(const float4*)(rp);
        float4 k4 = *(const float4*)(rp + 256);
        float4 v4 = *(const float4*)(rp + 512);
        Qs[row][c4 + 0] = tf32r(q4.x * scale);
        Qs[row][c4 + 1] = tf32r(q4.y * scale);
        Qs[row][c4 + 2] = tf32r(q4.z * scale);
        Qs[row][c4 + 3] = tf32r(q4.w * scale);
        Ks[row][c4 + 0] = tf32r(k4.x);
        Ks[row][c4 + 1] = tf32r(k4.y);
        Ks[row][c4 + 2] = tf32r(k4.z);
        Ks[row][c4 + 3] = tf32r(k4.w);
        Vs[row][c4 + 0] = tf32r(v4.x);
        Vs[row][c4 + 1] = tf32r(v4.y);
        Vs[row][c4 + 2] = tf32r(v4.z);
        Vs[row][c4 + 3] = tf32r(v4.w);
    }
    __syncthreads();

    const int lane = tid & 31, warp = tid >> 5;
    const int gid = lane >> 2, tig = lane & 3;
    const int mB = warp << 4;
    const int r0 = mB + gid, r1 = r0 + 8;

    // S = q*scale @ k^T  (64x64, each warp 16 rows)
    float c[8][4];
#pragma unroll
    for (int nf = 0; nf < 8; nf++)
#pragma unroll
        for (int r = 0; r < 4; r++) c[nf][r] = 0.f;

#pragma unroll
    for (int kc = 0; kc < 4; kc++) {
        uint32_t a[4];
        a[0] = __float_as_uint(Qs[r0][kc * 8 + tig]);
        a[1] = __float_as_uint(Qs[r1][kc * 8 + tig]);
        a[2] = __float_as_uint(Qs[r0][kc * 8 + tig + 4]);
        a[3] = __float_as_uint(Qs[r1][kc * 8 + tig + 4]);
#pragma unroll
        for (int nf = 0; nf < 8; nf++) {
            uint32_t bf[2];
            bf[0] = __float_as_uint(Ks[nf * 8 + gid][kc * 8 + tig]);
            bf[1] = __float_as_uint(Ks[nf * 8 + gid][kc * 8 + tig + 4]);
            mma8(c[nf], a, bf);
        }
    }

    // + bias, then row softmax (row r0 in c[.][0..1], row r1 in c[.][2..3])
    const float* bp = bias + (h << 12);
    float mx0 = -1e30f, mx1 = -1e30f;
#pragma unroll
    for (int nf = 0; nf < 8; nf++) {
        int col = nf * 8 + 2 * tig;
        float2 b0 = *(const float2*)(bp + r0 * 64 + col);
        float2 b1 = *(const float2*)(bp + r1 * 64 + col);
        c[nf][0] += b0.x; c[nf][1] += b0.y;
        c[nf][2] += b1.x; c[nf][3] += b1.y;
        mx0 = fmaxf(mx0, fmaxf(c[nf][0], c[nf][1]));
        mx1 = fmaxf(mx1, fmaxf(c[nf][2], c[nf][3]));
    }
    mx0 = fmaxf(mx0, __shfl_xor_sync(0xffffffffu, mx0, 1));
    mx0 = fmaxf(mx0, __shfl_xor_sync(0xffffffffu, mx0, 2));
    mx1 = fmaxf(mx1, __shfl_xor_sync(0xffffffffu, mx1, 1));
    mx1 = fmaxf(mx1, __shfl_xor_sync(0xffffffffu, mx1, 2));

    float s0 = 0.f, s1 = 0.f;
#pragma unroll
    for (int nf = 0; nf < 8; nf++) {
        c[nf][0] = __expf(c[nf][0] - mx0); s0 += c[nf][0];
        c[nf][1] = __expf(c[nf][1] - mx0); s0 += c[nf][1];
        c[nf][2] = __expf(c[nf][2] - mx1); s1 += c[nf][2];
        c[nf][3] = __expf(c[nf][3] - mx1); s1 += c[nf][3];
    }
    s0 += __shfl_xor_sync(0xffffffffu, s0, 1);
    s0 += __shfl_xor_sync(0xffffffffu, s0, 2);
    s1 += __shfl_xor_sync(0xffffffffu, s1, 1);
    s1 += __shfl_xor_sync(0xffffffffu, s1, 2);
    float i0 = 1.f / s0, i1 = 1.f / s1;

#pragma unroll
    for (int nf = 0; nf < 8; nf++) {
        int col = nf * 8 + 2 * tig;
        Ss[r0][col]     = tf32r(c[nf][0] * i0);
        Ss[r0][col + 1] = tf32r(c[nf][1] * i0);
        Ss[r1][col]     = tf32r(c[nf][2] * i1);
        Ss[r1][col + 1] = tf32r(c[nf][3] * i1);
    }
    __syncthreads();

    // O = P @ V  (64x32, each warp 16 rows)
    float o[4][4];
#pragma unroll
    for (int nf = 0; nf < 4; nf++)
#pragma unroll
        for (int r = 0; r < 4; r++) o[nf][r] = 0.f;

#pragma unroll
    for (int kc = 0; kc < 8; kc++) {
        uint32_t a[4];
        a[0] = __float_as_uint(Ss[r0][kc * 8 + tig]);
        a[1] = __float_as_uint(Ss[r1][kc * 8 + tig]);
        a[2] = __float_as_uint(Ss[r0][kc * 8 + tig + 4]);
        a[3] = __float_as_uint(Ss[r1][kc * 8 + tig + 4]);
#pragma unroll
        for (int nf = 0; nf < 4; nf++) {
            uint32_t bf[2];
            bf[0] = __float_as_uint(Vs[kc * 8 + tig    ][nf * 8 + gid]);
            bf[1] = __float_as_uint(Vs[kc * 8 + tig + 4][nf * 8 + gid]);
            mma8(o[nf], a, bf);
        }
    }

    // scatter to natural token order, [M, 256] at col h*32 + d
    const int l0 = base_l + ((r0 >> 3) << 8) + (r0 & 7);
    const int l1 = base_l + ((r1 >> 3) << 8) + (r1 & 7);
#pragma unroll
    for (int nf = 0; nf < 4; nf++) {
        int col = (h << 5) + nf * 8 + 2 * tig;
        *(float2*)(outp + (size_t)l0 * 256 + col) = make_float2(o[nf][0], o[nf][1]);
        *(float2*)(outp + (size_t)l1 * 256 + col) = make_float2(o[nf][2], o[nf][3]);
    }
}

// ---------------------------------------------------------------------------
// launch
// ---------------------------------------------------------------------------
extern "C" void kernel_launch(void* const* d_in, const int* in_sizes, int n_in,
                              void* d_out, int out_size)
{
    const float* x      = (const float*)d_in[0];
    const float* qkv_w  = (const float*)d_in[1];
    const float* proj_w = (const float*)d_in[2];
    const float* proj_b = (const float*)d_in[3];
    const float* bias   = (const float*)d_in[4];
    float* out = (float*)d_out;

    float *qkv_p, *att_p;
    cudaGetSymbolAddress((void**)&qkv_p, g_qkv);
    cudaGetSymbolAddress((void**)&att_p, g_att);

    // QKV projection: [262144,256] @ [768,256]^T -> [262144,768]
    gemm_tf32<<<dim3(768 / BN, Mtot / BM), 256>>>(x, qkv_w, nullptr, qkv_p,
                                                  Mtot, 768, C_);
    // window attention
    win_attn<<<dim3(NWIN, NH_), 128>>>(qkv_p, bias, att_p);
    // output projection: [262144,256] @ [256,256]^T + b -> d_out
    gemm_tf32<<<dim3(256 / BN, Mtot / BM), 256>>>(att_p, proj_w, proj_b, out,
                                                  Mtot, C_, C_);
}

// round 7
// speedup vs baseline: 1.3182x; 1.0179x over previous
#include <cuda_runtime.h>
#include <cuda_bf16.h>
#include <cstdint>
#include <cstddef>

// Problem constants
#define B_    4
#define Hdim  256
#define Wdim  256
#define C_    256
#define NH_   8
#define HD_   32
#define WS_   8
#define Mtot  262144          // B * H * W tokens
#define NWIN  4096            // B * 32 * 32 windows

// Scratch (allocation-free rule: __device__ globals)
__device__ float g_qkv[(size_t)Mtot * 768];   // natural token order, [M, 768] (q|k|v)
__device__ float g_att[(size_t)Mtot * 256];   // attention output, natural token order

// ---------------------------------------------------------------------------
// helpers
// ---------------------------------------------------------------------------
__device__ __forceinline__ float tf32r(float x) {
    uint32_t u;
    asm("cvt.rna.tf32.f32 %0, %1;" : "=r"(u) : "f"(x));
    return __uint_as_float(u);
}
__device__ __forceinline__ uint32_t tf32u(float x) {
    uint32_t u;
    asm("cvt.rna.tf32.f32 %0, %1;" : "=r"(u) : "f"(x));
    return u;
}

__device__ __forceinline__ void mma8(float c[4], const uint32_t a[4], const uint32_t b[2]) {
    asm volatile(
        "mma.sync.aligned.m16n8k8.row.col.f32.tf32.tf32.f32 "
        "{%0,%1,%2,%3}, {%4,%5,%6,%7}, {%8,%9}, {%0,%1,%2,%3};\n"
        : "+f"(c[0]), "+f"(c[1]), "+f"(c[2]), "+f"(c[3])
        : "r"(a[0]), "r"(a[1]), "r"(a[2]), "r"(a[3]), "r"(b[0]), "r"(b[1]));
}

__device__ __forceinline__ void cpa16(void* dst, const void* src) {
    uint32_t d = (uint32_t)__cvta_generic_to_shared(dst);
    asm volatile("cp.async.cg.shared.global [%0], [%1], 16;\n" :: "r"(d), "l"(src));
}
__device__ __forceinline__ void cpa_commit() {
    asm volatile("cp.async.commit_group;\n" ::: "memory");
}
template <int N>
__device__ __forceinline__ void cpa_wait() {
    asm volatile("cp.async.wait_group %0;\n" :: "n"(N) : "memory");
}

// ---------------------------------------------------------------------------
// TF32 GEMM, 2-stage cp.async pipeline:
// C[M,N] = A[M,K] @ B[N,K]^T (+ bias[N])
// BM=128, BN=128, BK=16, 128 threads, 4 warps (2x2), warp tile 64x64
// smem row-major [rows][KPAD=20]: 80B row stride -> conflict-free fragment LDS
// ---------------------------------------------------------------------------
#define BM 128
#define BN 128
#define BK 16
#define KPAD 20   // 20 floats = 80 bytes (16B multiple, conflict-free mod 32 banks)

__global__ __launch_bounds__(128) void gemm_tf32(
    const float* __restrict__ A, const float* __restrict__ Bm,
    const float* __restrict__ bias, float* __restrict__ C,
    int M, int N, int K)
{
    __shared__ __align__(16) float As[2][BM][KPAD];
    __shared__ __align__(16) float Bs[2][BN][KPAD];

    const int tid  = threadIdx.x;
    const int mT   = blockIdx.y * BM;
    const int nT   = blockIdx.x * BN;
    const int lane = tid & 31;
    const int warp = tid >> 5;
    const int gid  = lane >> 2;
    const int tig  = lane & 3;
    const int wm   = (warp & 1) * 64;
    const int wn   = (warp >> 1) * 64;

    float c[4][8][4];
#pragma unroll
    for (int i = 0; i < 4; i++)
#pragma unroll
        for (int j = 0; j < 8; j++)
#pragma unroll
            for (int r = 0; r < 4; r++) c[i][j][r] = 0.f;

    // copy map: 512 float4 per (A or B) tile, 4 per thread each
    const int rc = tid >> 2;             // base row 0..31
    const int cc = (tid & 3) << 2;       // 0,4,8,12

    auto issue = [&](int s, int k0) {
        const float* ab = A  + (size_t)(mT + rc) * K + k0 + cc;
        const float* bb = Bm + (size_t)(nT + rc) * K + k0 + cc;
#pragma unroll
        for (int it = 0; it < 4; it++) {
            int row = rc + it * 32;
            cpa16(&As[s][row][cc], ab + (size_t)it * 32 * K);
            cpa16(&Bs[s][row][cc], bb + (size_t)it * 32 * K);
        }
        cpa_commit();
    };

    issue(0, 0);
    const int NT = K >> 4;

    for (int kt = 0; kt < NT; kt++) {
        if (kt + 1 < NT) {
            issue((kt + 1) & 1, (kt + 1) * BK);
            cpa_wait<1>();
        } else {
            cpa_wait<0>();
        }
        __syncthreads();

        const int s = kt & 1;
#pragma unroll
        for (int kk = 0; kk < BK; kk += 8) {
            uint32_t af[4][4], bf[8][2];
#pragma unroll
            for (int mf = 0; mf < 4; mf++) {
                int m = wm + mf * 16 + gid;
                af[mf][0] = tf32u(As[s][m    ][kk + tig]);
                af[mf][1] = tf32u(As[s][m + 8][kk + tig]);
                af[mf][2] = tf32u(As[s][m    ][kk + tig + 4]);
                af[mf][3] = tf32u(As[s][m + 8][kk + tig + 4]);
            }
#pragma unroll
            for (int nf = 0; nf < 8; nf++) {
                int n = wn + nf * 8 + gid;
                bf[nf][0] = tf32u(Bs[s][n][kk + tig]);
                bf[nf][1] = tf32u(Bs[s][n][kk + tig + 4]);
            }
#pragma unroll
            for (int mf = 0; mf < 4; mf++)
#pragma unroll
                for (int nf = 0; nf < 8; nf++)
                    mma8(c[mf][nf], af[mf], bf[nf]);
        }
        __syncthreads();
    }

    // epilogue
#pragma unroll
    for (int mf = 0; mf < 4; mf++) {
#pragma unroll
        for (int nf = 0; nf < 8; nf++) {
            int row = mT + wm + mf * 16 + gid;
            int col = nT + wn + nf * 8 + 2 * tig;
            float b0 = 0.f, b1 = 0.f;
            if (bias) { b0 = bias[col]; b1 = bias[col + 1]; }
            float2 v0 = make_float2(c[mf][nf][0] + b0, c[mf][nf][1] + b1);
            float2 v1 = make_float2(c[mf][nf][2] + b0, c[mf][nf][3] + b1);
            *(float2*)(C + (size_t)row * N + col)       = v0;
            *(float2*)(C + (size_t)(row + 8) * N + col) = v1;
        }
    }
}

// ---------------------------------------------------------------------------
// Window attention: one CTA per (window, head), 128 threads (4 warps).
// Gathers q,k,v for the 64 window tokens, computes softmax(q k^T * s + bias) v
// with TF32 MMAs, scatters result to natural token order in g_att.
// ---------------------------------------------------------------------------
__global__ __launch_bounds__(128) void win_attn(
    const float* __restrict__ qkv, const float* __restrict__ bias,
    float* __restrict__ outp)
{
    __shared__ float Qs[64][36];
    __shared__ float Ks[64][36];
    __shared__ float Vs[64][36];
    __shared__ float Ss[64][68];

    const int w   = blockIdx.x;
    const int h   = blockIdx.y;
    const int b   = w >> 10;
    const int rem = w & 1023;
    const int wh  = rem >> 5;
    const int ww  = rem & 31;
    const int base_l = (b << 16) + (wh << 3) * 256 + (ww << 3);

    const int tid = threadIdx.x;
    const float scale = 0.17677669529663687f;   // 1/sqrt(32)

    // load q,k,v tiles (64 x 32 each), row-coalesced float4
#pragma unroll
    for (int it = 0; it < 4; it++) {
        int v   = tid + it * 128;               // 0..511
        int row = v >> 3;                       // token 0..63
        int c4  = (v & 7) << 2;                 // 0..28
        int l   = base_l + ((row >> 3) << 8) + (row & 7);
        const float* rp = qkv + (size_t)l * 768 + (h << 5) + c4;
        float4 q4 = *(const float4*)(rp);
        float4 k4 = *(const float4*)(rp + 256);
        float4 v4 = *(const float4*)(rp + 512);
        Qs[row][c4 + 0] = tf32r(q4.x * scale);
        Qs[row][c4 + 1] = tf32r(q4.y * scale);
        Qs[row][c4 + 2] = tf32r(q4.z * scale);
        Qs[row][c4 + 3] = tf32r(q4.w * scale);
        Ks[row][c4 + 0] = tf32r(k4.x);
        Ks[row][c4 + 1] = tf32r(k4.y);
        Ks[row][c4 + 2] = tf32r(k4.z);
        Ks[row][c4 + 3] = tf32r(k4.w);
        Vs[row][c4 + 0] = tf32r(v4.x);
        Vs[row][c4 + 1] = tf32r(v4.y);
        Vs[row][c4 + 2] = tf32r(v4.z);
        Vs[row][c4 + 3] = tf32r(v4.w);
    }
    __syncthreads();

    const int lane = tid & 31, warp = tid >> 5;
    const int gid = lane >> 2, tig = lane & 3;
    const int mB = warp << 4;
    const int r0 = mB + gid, r1 = r0 + 8;

    // S = q*scale @ k^T  (64x64, each warp 16 rows)
    float c[8][4];
#pragma unroll
    for (int nf = 0; nf < 8; nf++)
#pragma unroll
        for (int r = 0; r < 4; r++) c[nf][r] = 0.f;

#pragma unroll
    for (int kc = 0; kc < 4; kc++) {
        uint32_t a[4];
        a[0] = __float_as_uint(Qs[r0][kc * 8 + tig]);
        a[1] = __float_as_uint(Qs[r1][kc * 8 + tig]);
        a[2] = __float_as_uint(Qs[r0][kc * 8 + tig + 4]);
        a[3] = __float_as_uint(Qs[r1][kc * 8 + tig + 4]);
#pragma unroll
        for (int nf = 0; nf < 8; nf++) {
            uint32_t bf[2];
            bf[0] = __float_as_uint(Ks[nf * 8 + gid][kc * 8 + tig]);
            bf[1] = __float_as_uint(Ks[nf * 8 + gid][kc * 8 + tig + 4]);
            mma8(c[nf], a, bf);
        }
    }

    // + bias, then row softmax (row r0 in c[.][0..1], row r1 in c[.][2..3])
    const float* bp = bias + (h << 12);
    float mx0 = -1e30f, mx1 = -1e30f;
#pragma unroll
    for (int nf = 0; nf < 8; nf++) {
        int col = nf * 8 + 2 * tig;
        float2 b0 = *(const float2*)(bp + r0 * 64 + col);
        float2 b1 = *(const float2*)(bp + r1 * 64 + col);
        c[nf][0] += b0.x; c[nf][1] += b0.y;
        c[nf][2] += b1.x; c[nf][3] += b1.y;
        mx0 = fmaxf(mx0, fmaxf(c[nf][0], c[nf][1]));
        mx1 = fmaxf(mx1, fmaxf(c[nf][2], c[nf][3]));
    }
    mx0 = fmaxf(mx0, __shfl_xor_sync(0xffffffffu, mx0, 1));
    mx0 = fmaxf(mx0, __shfl_xor_sync(0xffffffffu, mx0, 2));
    mx1 = fmaxf(mx1, __shfl_xor_sync(0xffffffffu, mx1, 1));
    mx1 = fmaxf(mx1, __shfl_xor_sync(0xffffffffu, mx1, 2));

    float s0 = 0.f, s1 = 0.f;
#pragma unroll
    for (int nf = 0; nf < 8; nf++) {
        c[nf][0] = __expf(c[nf][0] - mx0); s0 += c[nf][0];
        c[nf][1] = __expf(c[nf][1] - mx0); s0 += c[nf][1];
        c[nf][2] = __expf(c[nf][2] - mx1); s1 += c[nf][2];
        c[nf][3] = __expf(c[nf][3] - mx1); s1 += c[nf][3];
    }
    s0 += __shfl_xor_sync(0xffffffffu, s0, 1);
    s0 += __shfl_xor_sync(0xffffffffu, s0, 2);
    s1 += __shfl_xor_sync(0xffffffffu, s1, 1);
    s1 += __shfl_xor_sync(0xffffffffu, s1, 2);
    float i0 = 1.f / s0, i1 = 1.f / s1;

#pragma unroll
    for (int nf = 0; nf < 8; nf++) {
        int col = nf * 8 + 2 * tig;
        Ss[r0][col]     = tf32r(c[nf][0] * i0);
        Ss[r0][col + 1] = tf32r(c[nf][1] * i0);
        Ss[r1][col]     = tf32r(c[nf][2] * i1);
        Ss[r1][col + 1] = tf32r(c[nf][3] * i1);
    }
    __syncthreads();

    // O = P @ V  (64x32, each warp 16 rows)
    float o[4][4];
#pragma unroll
    for (int nf = 0; nf < 4; nf++)
#pragma unroll
        for (int r = 0; r < 4; r++) o[nf][r] = 0.f;

#pragma unroll
    for (int kc = 0; kc < 8; kc++) {
        uint32_t a[4];
        a[0] = __float_as_uint(Ss[r0][kc * 8 + tig]);
        a[1] = __float_as_uint(Ss[r1][kc * 8 + tig]);
        a[2] = __float_as_uint(Ss[r0][kc * 8 + tig + 4]);
        a[3] = __float_as_uint(Ss[r1][kc * 8 + tig + 4]);
#pragma unroll
        for (int nf = 0; nf < 4; nf++) {
            uint32_t bf[2];
            bf[0] = __float_as_uint(Vs[kc * 8 + tig    ][nf * 8 + gid]);
            bf[1] = __float_as_uint(Vs[kc * 8 + tig + 4][nf * 8 + gid]);
            mma8(o[nf], a, bf);
        }
    }

    // scatter to natural token order, [M, 256] at col h*32 + d
    const int l0 = base_l + ((r0 >> 3) << 8) + (r0 & 7);
    const int l1 = base_l + ((r1 >> 3) << 8) + (r1 & 7);
#pragma unroll
    for (int nf = 0; nf < 4; nf++) {
        int col = (h << 5) + nf * 8 + 2 * tig;
        *(float2*)(outp + (size_t)l0 * 256 + col) = make_float2(o[nf][0], o[nf][1]);
        *(float2*)(outp + (size_t)l1 * 256 + col) = make_float2(o[nf][2], o[nf][3]);
    }
}

// ---------------------------------------------------------------------------
// launch
// ---------------------------------------------------------------------------
extern "C" void kernel_launch(void* const* d_in, const int* in_sizes, int n_in,
                              void* d_out, int out_size)
{
    const float* x      = (const float*)d_in[0];
    const float* qkv_w  = (const float*)d_in[1];
    const float* proj_w = (const float*)d_in[2];
    const float* proj_b = (const float*)d_in[3];
    const float* bias   = (const float*)d_in[4];
    float* out = (float*)d_out;

    float *qkv_p, *att_p;
    cudaGetSymbolAddress((void**)&qkv_p, g_qkv);
    cudaGetSymbolAddress((void**)&att_p, g_att);

    // QKV projection: [262144,256] @ [768,256]^T -> [262144,768]
    gemm_tf32<<<dim3(768 / BN, Mtot / BM), 128>>>(x, qkv_w, nullptr, qkv_p,
                                                  Mtot, 768, C_);
    // window attention
    win_attn<<<dim3(NWIN, NH_), 128>>>(qkv_p, bias, att_p);
    // output projection: [262144,256] @ [256,256]^T + b -> d_out
    gemm_tf32<<<dim3(256 / BN, Mtot / BM), 128>>>(att_p, proj_w, proj_b, out,
                                                  Mtot, C_, C_);
}